// round 7
// baseline (speedup 1.0000x reference)
#include <cuda_runtime.h>
#include <math.h>

#define SEQ   2048
#define BATCH 64
#define DIN   512
#define DH    512

typedef unsigned long long u64;

// ---------------- f32x2 packed helpers (GEMM only) ----------------
__device__ __forceinline__ u64 dupf(float x) {
    u64 d; asm("mov.b64 %0, {%1, %1};" : "=l"(d) : "f"(x)); return d;
}
__device__ __forceinline__ void fma2(u64& acc, u64 a, u64 b) {
    asm("fma.rn.f32x2 %0, %1, %2, %0;" : "+l"(acc) : "l"(a), "l"(b));
}
__device__ __forceinline__ float2 unpack2(u64 v) {
    float lo, hi;
    asm("mov.b64 {%0, %1}, %2;" : "=f"(lo), "=f"(hi) : "l"(v));
    return make_float2(lo, hi);
}

// ---------------- XLA fast tanh: clamp 7.99881172180175781, passthrough ----------------
__device__ __forceinline__ float xla_tanh(float x) {
    const float kClamp = 7.99881172180175781f;
    float ax = fabsf(x);
    float xc = fminf(fmaxf(x, -kClamp), kClamp);
    float x2 = xc * xc;
    float p = __fmaf_rn(x2, -2.76076847742355e-16f, 2.00018790482477e-13f);
    p = __fmaf_rn(x2, p, -8.60467152213735e-11f);
    p = __fmaf_rn(x2, p, 5.12229709037114e-08f);
    p = __fmaf_rn(x2, p, 1.48572235717979e-05f);
    p = __fmaf_rn(x2, p, 6.37261928875436e-04f);
    p = __fmaf_rn(x2, p, 4.89352455891786e-03f);
    p = xc * p;
    float q = __fmaf_rn(x2, 1.19825839466702e-06f, 1.18534705686654e-04f);
    q = __fmaf_rn(x2, q, 2.26843463243900e-03f);
    q = __fmaf_rn(x2, q, 4.89352518554385e-03f);
    float r = __fdiv_rn(p, q);
    return (ax < 0.0004f) ? x : r;
}

// ---------------- per-batch-group barrier (32 CTAs each, 8 groups) ----------------
__device__ unsigned g_cnt[8 * 32];
__device__ volatile unsigned g_gen[8 * 32];

__device__ __forceinline__ void bg_barrier(int bg) {
    __syncthreads();
    if (threadIdx.x == 0) {
        unsigned gen = g_gen[bg * 32];
        __threadfence();
        if (atomicAdd(&g_cnt[bg * 32], 1u) == 31u) {
            g_cnt[bg * 32] = 0;
            __threadfence();
            g_gen[bg * 32] = gen + 1u;
        } else {
            while (g_gen[bg * 32] == gen) { }
        }
        __threadfence();
    }
    __syncthreads();
}

// ---------------- Kernel 1: xi = x @ W_i2h^T + b_i2h (f32x2 packed) ----------------
#define BM 64
#define BN 64
#define BK 16

__global__ void __launch_bounds__(256) i2h_gemm_kernel(
    const float* __restrict__ A, const float* __restrict__ Bw,
    const float* __restrict__ bias, float* __restrict__ C)
{
    __shared__ float As[BK][BM + 4];
    __shared__ float Bs[BK][BN + 4];
    const int bm = blockIdx.x, bn = blockIdx.y, tid = threadIdx.x;
    const int tm = (tid / 16) * 4, tn = (tid % 16) * 4;
    const int lr = tid / 4, lk = (tid % 4) * 4;
    const float* Aptr = A + ((size_t)bm * BM + lr) * DIN + lk;
    const float* Bptr = Bw + ((size_t)bn * BN + lr) * DIN + lk;

    u64 acc2[4][2];
    #pragma unroll
    for (int i = 0; i < 4; i++) { acc2[i][0] = 0ull; acc2[i][1] = 0ull; }

    for (int k0 = 0; k0 < DIN; k0 += BK) {
        float4 av = *(const float4*)(Aptr + k0);
        float4 bv = *(const float4*)(Bptr + k0);
        As[lk + 0][lr] = av.x; As[lk + 1][lr] = av.y;
        As[lk + 2][lr] = av.z; As[lk + 3][lr] = av.w;
        Bs[lk + 0][lr] = bv.x; Bs[lk + 1][lr] = bv.y;
        Bs[lk + 2][lr] = bv.z; Bs[lk + 3][lr] = bv.w;
        __syncthreads();
        #pragma unroll
        for (int k = 0; k < BK; k++) {
            float4 a4 = *(const float4*)&As[k][tm];
            u64 b01 = *(const u64*)&Bs[k][tn];
            u64 b23 = *(const u64*)&Bs[k][tn + 2];
            float am[4] = {a4.x, a4.y, a4.z, a4.w};
            #pragma unroll
            for (int i = 0; i < 4; i++) {
                u64 ad = dupf(am[i]);
                fma2(acc2[i][0], ad, b01);
                fma2(acc2[i][1], ad, b23);
            }
        }
        __syncthreads();
    }

    const float b0 = bias[bn * BN + tn + 0];
    const float b1 = bias[bn * BN + tn + 1];
    const float b2 = bias[bn * BN + tn + 2];
    const float b3 = bias[bn * BN + tn + 3];
    #pragma unroll
    for (int i = 0; i < 4; i++) {
        float2 p0 = unpack2(acc2[i][0]);
        float2 p1 = unpack2(acc2[i][1]);
        float4 o;
        o.x = p0.x + b0;
        o.y = p0.y + b1;
        o.z = p1.x + b2;
        o.w = p1.y + b3;
        *(float4*)&C[((size_t)bm * BM + tm + i) * DH + bn * BN + tn] = o;
    }
}

// ---------------- Kernel 2: persistent scan, 256 CTAs (2/SM) ----------------
// Grid: bg(8 groups x 8 rows) x cg(32 groups x 16 cols) = 256 CTAs.
// CTA: 128 threads, warp tile 4 rows x 8 cols, 1 output/thread.
// Per output: ONE ascending-k fp32 FMA chain (init 0) -> (xi+dot)+b -> xla_tanh.
#define WST 516   // W_s row stride (col stride in floats)
#define HST 520   // h_s row stride

__global__ void __launch_bounds__(128, 2) rnn_scan_kernel(
    const float* __restrict__ h0, const float* __restrict__ W_h2h,
    const float* __restrict__ b_h2h, float* __restrict__ out,
    float* __restrict__ h_last)
{
    extern __shared__ float sm[];
    float* W_s = sm;                 // [16][WST]
    float* h_s = sm + 16 * WST;      // [8][HST]

    const int cg = blockIdx.x & 31;
    const int bg = blockIdx.x >> 5;
    const int c0 = cg * 16;
    const int b0 = bg * 8;
    const int tid = threadIdx.x;
    const int lane = tid & 31;
    const int w = tid >> 5;
    const int row = (w >> 1) * 4 + (lane >> 3);   // 0..7
    const int col = (w & 1) * 8 + (lane & 7);     // 0..15

    // stage W slice: W_s[c][k] = W_h2h[(c0+c)*DH + k]
    for (int idx = tid; idx < 16 * 512; idx += 128) {
        int c = idx >> 9, k = idx & 511;
        W_s[c * WST + k] = W_h2h[(size_t)(c0 + c) * DH + k];
    }
    const float bias = b_h2h[c0 + col];
    const float4* Wp = (const float4*)&W_s[col * WST];
    const float4* Hp = (const float4*)&h_s[row * HST];
    const size_t ooff = ((size_t)b0 + row) * DH + c0 + col;   // + t*BATCH*DH

    // prefetch xi for t=0
    float xi = out[ooff];
    __syncthreads();

    for (int t = 0; t < SEQ; t++) {
        // load h(t-1): 8 rows x 512 cols (1024 float4; 8 per thread)
        const float4* hsrc = (const float4*)((t == 0)
            ? (h0 + (size_t)b0 * DH)
            : (out + ((size_t)(t - 1) * BATCH + b0) * DH));
        #pragma unroll
        for (int j = 0; j < 8; j++) {
            int idx = tid + 128 * j;
            int r = idx >> 7, kq = idx & 127;
            float4 v = hsrc[r * 128 + kq];
            *(float4*)&h_s[r * HST + kq * 4] = v;
        }
        __syncthreads();

        // one ascending-k chain
        float acc = 0.f;
        #pragma unroll 8
        for (int k4 = 0; k4 < 128; k4++) {
            float4 wv = Wp[k4];
            float4 hv = Hp[k4];
            acc = __fmaf_rn(hv.x, wv.x, acc);
            acc = __fmaf_rn(hv.y, wv.y, acc);
            acc = __fmaf_rn(hv.z, wv.z, acc);
            acc = __fmaf_rn(hv.w, wv.w, acc);
        }

        float v = xla_tanh((xi + acc) + bias);
        out[(size_t)t * BATCH * DH + ooff] = v;
        if (t == SEQ - 1) {
            if (h_last) h_last[ooff] = v;
        } else {
            // prefetch xi(t+1) BEFORE the barrier (out[t+1] still holds xi)
            xi = out[(size_t)(t + 1) * BATCH * DH + ooff];
            bg_barrier(bg);
        }
    }
}

// ---------------- launch ----------------
extern "C" void kernel_launch(void* const* d_in, const int* in_sizes, int n_in,
                              void* d_out, int out_size) {
    const float* x     = (const float*)d_in[0];
    const float* h0    = (const float*)d_in[1];
    const float* W_i2h = (const float*)d_in[2];
    const float* b_i2h = (const float*)d_in[3];
    const float* W_h2h = (const float*)d_in[4];
    const float* b_h2h = (const float*)d_in[5];
    float* out = (float*)d_out;

    float* h_last = nullptr;
    if ((long long)out_size >= (long long)(SEQ + 1) * BATCH * DH)
        h_last = out + (size_t)SEQ * BATCH * DH;

    dim3 g1(SEQ * BATCH / BM, DH / BN);
    i2h_gemm_kernel<<<g1, 256>>>(x, W_i2h, b_i2h, out);

    const int smem = (16 * WST + 8 * HST) * sizeof(float);
    cudaFuncSetAttribute(rnn_scan_kernel,
                         cudaFuncAttributeMaxDynamicSharedMemorySize, smem);
    rnn_scan_kernel<<<256, 128, smem>>>(h0, W_h2h, b_h2h, out, h_last);
}

// round 9
// speedup vs baseline: 1.1355x; 1.1355x over previous
#include <cuda_runtime.h>
#include <math.h>

#define SEQ   2048
#define BATCH 64
#define DIN   512
#define DH    512

typedef unsigned long long u64;

// ---------------- f32x2 packed helpers ----------------
__device__ __forceinline__ u64 dupf(float x) {
    u64 d; asm("mov.b64 %0, {%1, %1};" : "=l"(d) : "f"(x)); return d;
}
__device__ __forceinline__ void fma2(u64& acc, u64 a, u64 b) {
    asm("fma.rn.f32x2 %0, %1, %2, %0;" : "+l"(acc) : "l"(a), "l"(b));
}
__device__ __forceinline__ float2 unpack2(u64 v) {
    float lo, hi;
    asm("mov.b64 {%0, %1}, %2;" : "=f"(lo), "=f"(hi) : "l"(v));
    return make_float2(lo, hi);
}

// ---------------- XLA fast tanh: clamp 7.99881172180175781, passthrough ----------------
__device__ __forceinline__ float xla_tanh(float x) {
    const float kClamp = 7.99881172180175781f;
    float ax = fabsf(x);
    float xc = fminf(fmaxf(x, -kClamp), kClamp);
    float x2 = xc * xc;
    float p = __fmaf_rn(x2, -2.76076847742355e-16f, 2.00018790482477e-13f);
    p = __fmaf_rn(x2, p, -8.60467152213735e-11f);
    p = __fmaf_rn(x2, p, 5.12229709037114e-08f);
    p = __fmaf_rn(x2, p, 1.48572235717979e-05f);
    p = __fmaf_rn(x2, p, 6.37261928875436e-04f);
    p = __fmaf_rn(x2, p, 4.89352455891786e-03f);
    p = xc * p;
    float q = __fmaf_rn(x2, 1.19825839466702e-06f, 1.18534705686654e-04f);
    q = __fmaf_rn(x2, q, 2.26843463243900e-03f);
    q = __fmaf_rn(x2, q, 4.89352518554385e-03f);
    float r = __fdiv_rn(p, q);
    return (ax < 0.0004f) ? x : r;
}

// ---------------- per-bg flag barrier state ----------------
// g_flag[(bg*16+cg)*32]: last completed step per CTA. Deterministic reset:
// scan epilogue (t == SEQ-1) resets its own flag to 0, so every graph replay
// starts from a clean state.
__device__ volatile unsigned g_flag[8 * 16 * 32];

// ---------------- Kernel 1: xi = x @ W_i2h^T + b_i2h (f32x2 packed) ----------------
#define BM 64
#define BN 64
#define BK 16

__global__ void __launch_bounds__(256) i2h_gemm_kernel(
    const float* __restrict__ A, const float* __restrict__ Bw,
    const float* __restrict__ bias, float* __restrict__ C)
{
    __shared__ float As[BK][BM + 4];
    __shared__ float Bs[BK][BN + 4];
    const int bm = blockIdx.x, bn = blockIdx.y, tid = threadIdx.x;
    const int tm = (tid / 16) * 4, tn = (tid % 16) * 4;
    const int lr = tid / 4, lk = (tid % 4) * 4;
    const float* Aptr = A + ((size_t)bm * BM + lr) * DIN + lk;
    const float* Bptr = Bw + ((size_t)bn * BN + lr) * DIN + lk;

    u64 acc2[4][2];
    #pragma unroll
    for (int i = 0; i < 4; i++) { acc2[i][0] = 0ull; acc2[i][1] = 0ull; }

    for (int k0 = 0; k0 < DIN; k0 += BK) {
        float4 av = *(const float4*)(Aptr + k0);
        float4 bv = *(const float4*)(Bptr + k0);
        As[lk + 0][lr] = av.x; As[lk + 1][lr] = av.y;
        As[lk + 2][lr] = av.z; As[lk + 3][lr] = av.w;
        Bs[lk + 0][lr] = bv.x; Bs[lk + 1][lr] = bv.y;
        Bs[lk + 2][lr] = bv.z; Bs[lk + 3][lr] = bv.w;
        __syncthreads();
        #pragma unroll
        for (int k = 0; k < BK; k++) {
            float4 a4 = *(const float4*)&As[k][tm];
            u64 b01 = *(const u64*)&Bs[k][tn];
            u64 b23 = *(const u64*)&Bs[k][tn + 2];
            float am[4] = {a4.x, a4.y, a4.z, a4.w};
            #pragma unroll
            for (int i = 0; i < 4; i++) {
                u64 ad = dupf(am[i]);
                fma2(acc2[i][0], ad, b01);
                fma2(acc2[i][1], ad, b23);
            }
        }
        __syncthreads();
    }

    const float b0 = bias[bn * BN + tn + 0];
    const float b1 = bias[bn * BN + tn + 1];
    const float b2 = bias[bn * BN + tn + 2];
    const float b3 = bias[bn * BN + tn + 3];
    #pragma unroll
    for (int i = 0; i < 4; i++) {
        float2 p0 = unpack2(acc2[i][0]);
        float2 p1 = unpack2(acc2[i][1]);
        float4 o;
        o.x = p0.x + b0;
        o.y = p0.y + b1;
        o.z = p1.x + b2;
        o.w = p1.y + b3;
        *(float4*)&C[((size_t)bm * BM + tm + i) * DH + bn * BN + tn] = o;
    }
}

// ---------------- Kernel 2: persistent scan (f32x2 chains, W pair-dedup) ----------------
// 128 CTAs = bg(8 x 8 rows) x cg(16 x 32 cols). 128 threads = 4 warps.
// Warp w: col-pairs P = 4w + (lane&3); row r = lane>>2. Thread -> outputs (c, c+1).
// Per output: one ascending-k fp32 chain (f32x2 lane) -> (xi+dot)+b -> xla_tanh.
#define WPST 257   // W pair stride in float4
#define HST4 129   // h row stride in float4

__global__ void __launch_bounds__(128, 1) rnn_scan_kernel(
    const float* __restrict__ h0, const float* __restrict__ W_h2h,
    const float* __restrict__ b_h2h, float* __restrict__ out,
    float* __restrict__ h_last)
{
    extern __shared__ float4 sm4[];
    float4* W4s = sm4;               // [16][WPST]
    float4* h4s = sm4 + 16 * WPST;   // [8][HST4]

    const int cg = blockIdx.x & 15;
    const int bg = blockIdx.x >> 4;
    const int c0 = cg * 32;
    const int b0 = bg * 8;
    const int tid = threadIdx.x;
    const int lane = tid & 31;
    const int warp = tid >> 5;
    const int P = warp * 4 + (lane & 3);     // col-pair 0..15
    const int r = lane >> 2;                 // row 0..7
    const int c = c0 + 2 * P;

    // stage W interleaved: W4s[P][k2] = (W[c][2k2], W[c+1][2k2], W[c][2k2+1], W[c+1][2k2+1])
    for (int idx = tid; idx < 16 * 256; idx += 128) {
        int p = idx >> 8, k2 = idx & 255;
        float2 a = *(const float2*)(W_h2h + (size_t)(c0 + 2 * p) * DH + 2 * k2);
        float2 b = *(const float2*)(W_h2h + (size_t)(c0 + 2 * p + 1) * DH + 2 * k2);
        W4s[p * WPST + k2] = make_float4(a.x, b.x, a.y, b.y);
    }

    const float bias0 = b_h2h[c];
    const float bias1 = b_h2h[c + 1];
    const ulonglong2* Wp = (const ulonglong2*)(W4s + (size_t)P * WPST);
    const float4* Hp = h4s + (size_t)r * HST4;
    const size_t rowoff = (size_t)(b0 + r) * DH + c;   // + t*BATCH*DH

    // h-load mapping: thread covers row lr, 8 strided float4s
    const int lr = tid >> 4;
    const int kc = tid & 15;

    // prefetch xi for t=0 (GEMM completed before this kernel on the same stream)
    float2 xi = *(const float2*)(out + rowoff);
    __syncthreads();

    for (int t = 0; t < SEQ; t++) {
        // load h(t-1) rows into smem
        const float4* hsrc = (const float4*)((t == 0)
            ? (h0 + (size_t)(b0 + lr) * DH)
            : (out + ((size_t)(t - 1) * BATCH + b0 + lr) * DH));
        float4* hdst = h4s + lr * HST4;
        #pragma unroll
        for (int j = 0; j < 8; j++)
            hdst[kc + 16 * j] = hsrc[kc + 16 * j];
        __syncthreads();

        // two ascending-k chains packed in one fma.rn.f32x2 stream
        u64 acc = 0ull;
        #pragma unroll 16
        for (int k4 = 0; k4 < 128; k4++) {
            float4 hv = Hp[k4];
            ulonglong2 w0 = Wp[2 * k4];
            ulonglong2 w1 = Wp[2 * k4 + 1];
            fma2(acc, dupf(hv.x), w0.x);
            fma2(acc, dupf(hv.y), w0.y);
            fma2(acc, dupf(hv.z), w1.x);
            fma2(acc, dupf(hv.w), w1.y);
        }
        float2 d = unpack2(acc);
        float v0 = xla_tanh((xi.x + d.x) + bias0);
        float v1 = xla_tanh((xi.y + d.y) + bias1);
        *(float2*)(out + (size_t)t * BATCH * DH + rowoff) = make_float2(v0, v1);

        if (t == SEQ - 1) {
            if (h_last) *(float2*)(h_last + rowoff) = make_float2(v0, v1);
            // reset my flag for the next graph replay (deterministic state)
            __syncthreads();
            if (tid == 0) g_flag[(bg * 16 + cg) * 32] = 0u;
        } else {
            // prefetch xi(t+1) BEFORE the barrier (out[t+1] untouched until t+1)
            xi = *(const float2*)(out + (size_t)(t + 1) * BATCH * DH + rowoff);
            __threadfence();
            __syncthreads();
            if (tid == 0) g_flag[(bg * 16 + cg) * 32] = (unsigned)(t + 1);
            if (tid < 16) {
                volatile unsigned* f = &g_flag[(bg * 16 + tid) * 32];
                while (*f < (unsigned)(t + 1)) { }
            }
            __threadfence();
            __syncthreads();
        }
    }
}

// ---------------- launch (single stream, graph-capture-safe) ----------------
extern "C" void kernel_launch(void* const* d_in, const int* in_sizes, int n_in,
                              void* d_out, int out_size) {
    const float* x     = (const float*)d_in[0];
    const float* h0    = (const float*)d_in[1];
    const float* W_i2h = (const float*)d_in[2];
    const float* b_i2h = (const float*)d_in[3];
    const float* W_h2h = (const float*)d_in[4];
    const float* b_h2h = (const float*)d_in[5];
    float* out = (float*)d_out;

    float* h_last = nullptr;
    if ((long long)out_size >= (long long)(SEQ + 1) * BATCH * DH)
        h_last = out + (size_t)SEQ * BATCH * DH;

    dim3 g1(SEQ * BATCH / BM, DH / BN);
    i2h_gemm_kernel<<<g1, 256>>>(x, W_i2h, b_i2h, out);

    const int smem = (16 * WPST + 8 * HST4) * 16;
    cudaFuncSetAttribute(rnn_scan_kernel,
                         cudaFuncAttributeMaxDynamicSharedMemorySize, smem);
    rnn_scan_kernel<<<128, 128, smem>>>(h0, W_h2h, b_h2h, out, h_last);
}